// round 8
// baseline (speedup 1.0000x reference)
#include <cuda_runtime.h>
#include <cuda_bf16.h>
#include <cstdint>

constexpr int Bc = 4, Sc = 128, Hc = 32, Dc = 128, Tc = 2048;
constexpr int HD  = Hc * Dc;          // 4096
constexpr int KVB = 64;

// smem (bytes): Q hi/lo + bf16 K/V tiles + fp32 cp.async staging
constexpr uint32_t QHI  = 0;          // 128x128 bf16 = 32KB
constexpr uint32_t QLO  = 32768;
constexpr uint32_t KHI  = 65536;      // 64x128 bf16 = 16KB
constexpr uint32_t KLO  = 81920;
constexpr uint32_t VHI  = 98304;
constexpr uint32_t VLO  = 114688;
constexpr uint32_t STGK = 131072;     // 64x128 fp32 = 32KB
constexpr uint32_t STGV = 163840;
constexpr uint32_t SMEM_BYTES = 196608;

__device__ __forceinline__ uint32_t swz_w(int r, int d0) {   // 8B store addr
    return (uint32_t)(r * 256 + ((((d0 >> 3)) ^ (r & 7)) << 4) + ((d0 & 7) << 1));
}
__device__ __forceinline__ uint32_t swz_l(int r, int c0) {   // ldmatrix row addr
    return (uint32_t)(r * 256 + ((((c0 >> 3)) ^ (r & 7)) << 4));
}
__device__ __forceinline__ uint32_t smem_u32(const void* p) {
    uint32_t r;
    asm("{\n\t.reg .u64 t;\n\tcvta.to.shared.u64 t, %1;\n\tcvt.u32.u64 %0, t;\n\t}"
        : "=r"(r) : "l"(p));
    return r;
}

#define LDSM4(R0,R1,R2,R3,A) \
    asm volatile("ldmatrix.sync.aligned.m8n8.x4.shared.b16 {%0,%1,%2,%3}, [%4];" \
        : "=r"(R0),"=r"(R1),"=r"(R2),"=r"(R3) : "r"(A))
#define LDSM4T(R0,R1,R2,R3,A) \
    asm volatile("ldmatrix.sync.aligned.m8n8.x4.trans.shared.b16 {%0,%1,%2,%3}, [%4];" \
        : "=r"(R0),"=r"(R1),"=r"(R2),"=r"(R3) : "r"(A))
#define MMA(C,A0,A1,A2,A3,B0,B1) \
    asm volatile("mma.sync.aligned.m16n8k16.row.col.f32.bf16.bf16.f32 " \
        "{%0,%1,%2,%3}, {%4,%5,%6,%7}, {%8,%9}, {%0,%1,%2,%3};" \
        : "+f"((C)[0]),"+f"((C)[1]),"+f"((C)[2]),"+f"((C)[3]) \
        : "r"(A0),"r"(A1),"r"(A2),"r"(A3),"r"(B0),"r"(B1))

__device__ __forceinline__ void cp16(uint32_t dst, const void* src, uint32_t sz) {
    asm volatile("cp.async.cg.shared.global [%0], [%1], 16, %2;"
                 :: "r"(dst), "l"(src), "r"(sz) : "memory");
}
__device__ __forceinline__ void cp_commit() { asm volatile("cp.async.commit_group;" ::: "memory"); }
__device__ __forceinline__ void cp_wait0()  { asm volatile("cp.async.wait_group 0;" ::: "memory"); }

__device__ __forceinline__ uint32_t pk_us(unsigned short a, unsigned short b) {
    return (uint32_t)a | ((uint32_t)b << 16);
}
__device__ __forceinline__ void split2(float2 v, uint32_t& hi, uint32_t& lo) {
    __nv_bfloat16 h0 = __float2bfloat16(v.x), h1 = __float2bfloat16(v.y);
    hi = pk_us(__bfloat16_as_ushort(h0), __bfloat16_as_ushort(h1));
    lo = pk_us(__bfloat16_as_ushort(__float2bfloat16(v.x - __bfloat162float(h0))),
               __bfloat16_as_ushort(__float2bfloat16(v.y - __bfloat162float(h1))));
}
__device__ __forceinline__ void split4(float4 v, uint2& hi, uint2& lo) {
    uint32_t h0, l0, h1, l1;
    split2(make_float2(v.x, v.y), h0, l0);
    split2(make_float2(v.z, v.w), h1, l1);
    hi = make_uint2(h0, h1); lo = make_uint2(l0, l1);
}

__global__ void __launch_bounds__(256, 1)
sdpa_hmma3_kernel(const float* __restrict__ gq, const float* __restrict__ gk,
                  const float* __restrict__ gv, const float* __restrict__ gkc,
                  const float* __restrict__ gvc, const int* __restrict__ gpos,
                  float* __restrict__ gout)
{
    extern __shared__ char smc[];
    const uint32_t sb = smem_u32(smc);
    const int tid = threadIdx.x;
    const int wid = tid >> 5;
    const int l   = tid & 31;
    const int bh = blockIdx.x, b = bh >> 5, h = bh & 31;

    const int start = *gpos;
    const int nkv   = start + Sc;
    const int nblk  = (nkv + KVB - 1) / KVB;

    const float* qb  = gq  + ((size_t)(b * Sc) * Hc + h) * Dc;
    const float* kcb = gkc + ((size_t)(b * Tc) * Hc + h) * Dc;
    const float* vcb = gvc + ((size_t)(b * Tc) * Hc + h) * Dc;
    const float* knb = gk  + ((size_t)(b * Sc) * Hc + h) * Dc;
    const float* vnb = gv  + ((size_t)(b * Sc) * Hc + h) * Dc;

    // ---- cp.async block 0 into staging ----
    {
        #pragma unroll
        for (int it = 0; it < 8; it++) {
            int idx = tid + it * 256;
            int key = idx >> 5, d = (idx & 31) * 4;
            int jg  = key;
            const float* ks; const float* vs; uint32_t sz = 16;
            if (jg < start)    { ks = kcb + (size_t)jg * HD + d;           vs = vcb + (size_t)jg * HD + d; }
            else if (jg < nkv) { ks = knb + (size_t)(jg - start) * HD + d; vs = vnb + (size_t)(jg - start) * HD + d; }
            else               { ks = kcb; vs = vcb; sz = 0; }
            cp16(sb + STGK + (uint32_t)idx * 16, ks, sz);
            cp16(sb + STGV + (uint32_t)idx * 16, vs, sz);
        }
        cp_commit();
    }

    // ---- prologue: Q -> smem hi/lo, scale folded in ----
    const float SCALE = 0.08838834764831845f;    // 1/sqrt(128)
    #pragma unroll
    for (int it = 0; it < 16; it++) {
        int idx = tid + it * 256;
        int r = idx >> 5, d = (idx & 31) * 4;
        float4 qv = *(const float4*)(qb + (size_t)r * HD + d);
        qv.x *= SCALE; qv.y *= SCALE; qv.z *= SCALE; qv.w *= SCALE;
        uint2 hi, lo; split4(qv, hi, lo);
        uint32_t o = swz_w(r, d);
        *(uint2*)(smc + QHI + o) = hi;
        *(uint2*)(smc + QLO + o) = lo;
    }

    float O[16][4];
    #pragma unroll
    for (int t = 0; t < 16; t++) { O[t][0]=O[t][1]=O[t][2]=O[t][3]=0.f; }
    float lacc0 = 0.f, lacc1 = 0.f;

    // fragment address constants
    const int q0   = wid * 16;
    const int row0 = q0 + (l >> 2);
    const int qrow = q0 + (l & 15);
    const int qc8  = (l >> 4) << 3;
    const int krow = (l & 7) + ((l >> 4) << 3);
    const int kc8  = ((l >> 3) & 1) << 3;
    const int vrow = (l & 7) + (((l >> 3) & 1) << 3);
    const int vc8  = (l >> 4) << 3;
    const int colb = (l & 3) * 2;

    // ---- convert block 0 staging -> bf16 bufs (also publishes Q) ----
    cp_wait0();
    __syncthreads();
    #pragma unroll
    for (int it = 0; it < 8; it++) {
        int idx = tid + it * 256;
        int key = idx >> 5, d = (idx & 31) * 4;
        uint32_t o = swz_w(key, d);
        uint2 hi, lo;
        split4(*(const float4*)(smc + STGK + (size_t)idx * 16), hi, lo);
        *(uint2*)(smc + KHI + o) = hi; *(uint2*)(smc + KLO + o) = lo;
        split4(*(const float4*)(smc + STGV + (size_t)idx * 16), hi, lo);
        *(uint2*)(smc + VHI + o) = hi; *(uint2*)(smc + VLO + o) = lo;
    }
    __syncthreads();

    for (int blk = 0; blk < nblk; blk++) {
        const int t0 = blk * KVB;
        const bool pf = (blk + 1) < nblk;

        // ---- cp.async next block into staging (background) ----
        if (pf) {
            const int t0n = t0 + KVB;
            #pragma unroll
            for (int it = 0; it < 8; it++) {
                int idx = tid + it * 256;
                int key = idx >> 5, d = (idx & 31) * 4;
                int jg  = t0n + key;
                const float* ks; const float* vs; uint32_t sz = 16;
                if (jg < start)    { ks = kcb + (size_t)jg * HD + d;           vs = vcb + (size_t)jg * HD + d; }
                else if (jg < nkv) { ks = knb + (size_t)(jg - start) * HD + d; vs = vnb + (size_t)(jg - start) * HD + d; }
                else               { ks = kcb; vs = vcb; sz = 0; }
                cp16(sb + STGK + (uint32_t)idx * 16, ks, sz);
                cp16(sb + STGV + (uint32_t)idx * 16, vs, sz);
            }
            cp_commit();
        }

        // ---- QK^T: Q frags from smem per kstep; term-major MMAs ----
        float S[8][4];
        #pragma unroll
        for (int t = 0; t < 8; t++) { S[t][0]=S[t][1]=S[t][2]=S[t][3]=0.f; }

        #pragma unroll
        for (int ks = 0; ks < 8; ks++) {
            uint32_t qh0,qh1,qh2,qh3, ql0,ql1,ql2,ql3;
            uint32_t qo = swz_l(qrow, ks * 16 + qc8);
            LDSM4(qh0,qh1,qh2,qh3, sb + QHI + qo);
            LDSM4(ql0,ql1,ql2,ql3, sb + QLO + qo);
            uint32_t kh[4][4], kl[4][4];
            int c0k = ks * 16 + kc8;
            #pragma unroll
            for (int np = 0; np < 4; np++) {
                uint32_t ko = swz_l(np * 16 + krow, c0k);
                LDSM4(kh[np][0],kh[np][1],kh[np][2],kh[np][3], sb + KHI + ko);
                LDSM4(kl[np][0],kl[np][1],kl[np][2],kl[np][3], sb + KLO + ko);
            }
            #pragma unroll
            for (int np = 0; np < 4; np++) {   // term hi x hi
                MMA(S[2*np  ], qh0,qh1,qh2,qh3, kh[np][0],kh[np][1]);
                MMA(S[2*np+1], qh0,qh1,qh2,qh3, kh[np][2],kh[np][3]);
            }
            #pragma unroll
            for (int np = 0; np < 4; np++) {   // term hi x lo
                MMA(S[2*np  ], qh0,qh1,qh2,qh3, kl[np][0],kl[np][1]);
                MMA(S[2*np+1], qh0,qh1,qh2,qh3, kl[np][2],kl[np][3]);
            }
            #pragma unroll
            for (int np = 0; np < 4; np++) {   // term lo x hi
                MMA(S[2*np  ], ql0,ql1,ql2,ql3, kh[np][0],kh[np][1]);
                MMA(S[2*np+1], ql0,ql1,ql2,ql3, kh[np][2],kh[np][3]);
            }
        }

        // ---- softmax (no max-subtraction; scale folded into Q) ----
        uint32_t ph[4][4], pl[4][4];
        #pragma unroll
        for (int nt = 0; nt < 8; nt++) {
            int j0 = t0 + nt * 8 + colb - start;
            float p0 = (j0     > row0    ) ? 0.f : __expf(S[nt][0]);
            float p1 = (j0 + 1 > row0    ) ? 0.f : __expf(S[nt][1]);
            float p2 = (j0     > row0 + 8) ? 0.f : __expf(S[nt][2]);
            float p3 = (j0 + 1 > row0 + 8) ? 0.f : __expf(S[nt][3]);
            lacc0 += p0 + p1;  lacc1 += p2 + p3;
            __nv_bfloat16 b0 = __float2bfloat16(p0), b1 = __float2bfloat16(p1);
            __nv_bfloat16 b2 = __float2bfloat16(p2), b3 = __float2bfloat16(p3);
            int kg = nt >> 1, sl = (nt & 1) * 2;
            ph[kg][sl  ] = pk_us(__bfloat16_as_ushort(b0), __bfloat16_as_ushort(b1));
            ph[kg][sl+1] = pk_us(__bfloat16_as_ushort(b2), __bfloat16_as_ushort(b3));
            pl[kg][sl  ] = pk_us(
                __bfloat16_as_ushort(__float2bfloat16(p0 - __bfloat162float(b0))),
                __bfloat16_as_ushort(__float2bfloat16(p1 - __bfloat162float(b1))));
            pl[kg][sl+1] = pk_us(
                __bfloat16_as_ushort(__float2bfloat16(p2 - __bfloat162float(b2))),
                __bfloat16_as_ushort(__float2bfloat16(p3 - __bfloat162float(b3))));
        }

        // ---- PV: d-tile pairs, term-major ----
        #pragma unroll
        for (int kg = 0; kg < 4; kg++) {
            int vr = kg * 16 + vrow;
            #pragma unroll
            for (int dq = 0; dq < 4; dq++) {
                uint32_t vh[2][4], vl[2][4];
                #pragma unroll
                for (int u = 0; u < 2; u++) {
                    uint32_t vo = swz_l(vr, (dq * 2 + u) * 16 + vc8);
                    LDSM4T(vh[u][0],vh[u][1],vh[u][2],vh[u][3], sb + VHI + vo);
                    LDSM4T(vl[u][0],vl[u][1],vl[u][2],vl[u][3], sb + VLO + vo);
                }
                #pragma unroll
                for (int u = 0; u < 2; u++) {
                    MMA(O[2*(dq*2+u)  ], ph[kg][0],ph[kg][1],ph[kg][2],ph[kg][3], vh[u][0],vh[u][1]);
                    MMA(O[2*(dq*2+u)+1], ph[kg][0],ph[kg][1],ph[kg][2],ph[kg][3], vh[u][2],vh[u][3]);
                }
                #pragma unroll
                for (int u = 0; u < 2; u++) {
                    MMA(O[2*(dq*2+u)  ], ph[kg][0],ph[kg][1],ph[kg][2],ph[kg][3], vl[u][0],vl[u][1]);
                    MMA(O[2*(dq*2+u)+1], ph[kg][0],ph[kg][1],ph[kg][2],ph[kg][3], vl[u][2],vl[u][3]);
                }
                #pragma unroll
                for (int u = 0; u < 2; u++) {
                    MMA(O[2*(dq*2+u)  ], pl[kg][0],pl[kg][1],pl[kg][2],pl[kg][3], vh[u][0],vh[u][1]);
                    MMA(O[2*(dq*2+u)+1], pl[kg][0],pl[kg][1],pl[kg][2],pl[kg][3], vh[u][2],vh[u][3]);
                }
            }
        }

        // ---- wait staging, convert for next block ----
        if (pf) {
            cp_wait0();
            __syncthreads();
            #pragma unroll
            for (int it = 0; it < 8; it++) {
                int idx = tid + it * 256;
                int key = idx >> 5, d = (idx & 31) * 4;
                uint32_t o = swz_w(key, d);
                uint2 hi, lo;
                split4(*(const float4*)(smc + STGK + (size_t)idx * 16), hi, lo);
                *(uint2*)(smc + KHI + o) = hi; *(uint2*)(smc + KLO + o) = lo;
                split4(*(const float4*)(smc + STGV + (size_t)idx * 16), hi, lo);
                *(uint2*)(smc + VHI + o) = hi; *(uint2*)(smc + VLO + o) = lo;
            }
            __syncthreads();
        }
    }

    // ---- epilogue: quad row-sum reduce, normalize, store ----
    lacc0 += __shfl_xor_sync(0xffffffffu, lacc0, 1);
    lacc0 += __shfl_xor_sync(0xffffffffu, lacc0, 2);
    lacc1 += __shfl_xor_sync(0xffffffffu, lacc1, 1);
    lacc1 += __shfl_xor_sync(0xffffffffu, lacc1, 2);
    const float inv0 = 1.f / lacc0, inv1 = 1.f / lacc1;

    float* o0 = gout + ((size_t)(b * Sc + row0    ) * HD) + h * Dc;
    float* o1 = gout + ((size_t)(b * Sc + row0 + 8) * HD) + h * Dc;
    #pragma unroll
    for (int nt = 0; nt < 16; nt++) {
        int d = nt * 8 + colb;
        *(float2*)(o0 + d) = make_float2(O[nt][0] * inv0, O[nt][1] * inv0);
        *(float2*)(o1 + d) = make_float2(O[nt][2] * inv1, O[nt][3] * inv1);
    }
}

extern "C" void kernel_launch(void* const* d_in, const int* in_sizes, int n_in,
                              void* d_out, int out_size)
{
    const float* q  = (const float*)d_in[0];
    const float* k  = (const float*)d_in[1];
    const float* v  = (const float*)d_in[2];
    const float* kc = (const float*)d_in[3];
    const float* vc = (const float*)d_in[4];
    const int*  pos = (const int*)d_in[5];
    float* out = (float*)d_out;

    cudaFuncSetAttribute(sdpa_hmma3_kernel,
                         cudaFuncAttributeMaxDynamicSharedMemorySize, SMEM_BYTES);
    sdpa_hmma3_kernel<<<Bc * Hc, 256, SMEM_BYTES>>>(q, k, v, kc, vc, pos, out);
}

// round 9
// speedup vs baseline: 1.1522x; 1.1522x over previous
#include <cuda_runtime.h>
#include <cuda_bf16.h>
#include <cstdint>

constexpr int Bc = 4, Sc = 128, Hc = 32, Dc = 128, Tc = 2048;
constexpr int HD  = Hc * Dc;          // 4096
constexpr int KVB = 64;

// smem (bytes): double-buffered bf16 K/V tiles + fp32 cp.async staging
constexpr uint32_t KHI  = 0;          // 2 x (64x128 bf16 = 16KB)
constexpr uint32_t KLO  = 32768;
constexpr uint32_t VHI  = 65536;
constexpr uint32_t VLO  = 98304;
constexpr uint32_t STGK = 131072;     // 64x128 fp32 = 32KB
constexpr uint32_t STGV = 163840;
constexpr uint32_t BUFS = 16384;      // per-buffer stride
constexpr uint32_t SMEM_BYTES = 196608;

__device__ __forceinline__ uint32_t swz_w(int r, int d0) {   // 8B store addr
    return (uint32_t)(r * 256 + ((((d0 >> 3)) ^ (r & 7)) << 4) + ((d0 & 7) << 1));
}
__device__ __forceinline__ uint32_t swz_l(int r, int c0) {   // ldmatrix row addr
    return (uint32_t)(r * 256 + ((((c0 >> 3)) ^ (r & 7)) << 4));
}
__device__ __forceinline__ uint32_t smem_u32(const void* p) {
    uint32_t r;
    asm("{\n\t.reg .u64 t;\n\tcvta.to.shared.u64 t, %1;\n\tcvt.u32.u64 %0, t;\n\t}"
        : "=r"(r) : "l"(p));
    return r;
}

#define LDSM4(R0,R1,R2,R3,A) \
    asm volatile("ldmatrix.sync.aligned.m8n8.x4.shared.b16 {%0,%1,%2,%3}, [%4];" \
        : "=r"(R0),"=r"(R1),"=r"(R2),"=r"(R3) : "r"(A))
#define LDSM4T(R0,R1,R2,R3,A) \
    asm volatile("ldmatrix.sync.aligned.m8n8.x4.trans.shared.b16 {%0,%1,%2,%3}, [%4];" \
        : "=r"(R0),"=r"(R1),"=r"(R2),"=r"(R3) : "r"(A))
#define MMA(C,A0,A1,A2,A3,B0,B1) \
    asm volatile("mma.sync.aligned.m16n8k16.row.col.f32.bf16.bf16.f32 " \
        "{%0,%1,%2,%3}, {%4,%5,%6,%7}, {%8,%9}, {%0,%1,%2,%3};" \
        : "+f"((C)[0]),"+f"((C)[1]),"+f"((C)[2]),"+f"((C)[3]) \
        : "r"(A0),"r"(A1),"r"(A2),"r"(A3),"r"(B0),"r"(B1))

__device__ __forceinline__ void cp16(uint32_t dst, const void* src) {
    asm volatile("cp.async.cg.shared.global [%0], [%1], 16;"
                 :: "r"(dst), "l"(src) : "memory");
}
__device__ __forceinline__ void cp_commit() { asm volatile("cp.async.commit_group;" ::: "memory"); }
__device__ __forceinline__ void cp_wait0()  { asm volatile("cp.async.wait_group 0;" ::: "memory"); }

__device__ __forceinline__ uint32_t pk_us(unsigned short a, unsigned short b) {
    return (uint32_t)a | ((uint32_t)b << 16);
}
__device__ __forceinline__ void split2(float2 v, uint32_t& hi, uint32_t& lo) {
    __nv_bfloat16 h0 = __float2bfloat16(v.x), h1 = __float2bfloat16(v.y);
    hi = pk_us(__bfloat16_as_ushort(h0), __bfloat16_as_ushort(h1));
    lo = pk_us(__bfloat16_as_ushort(__float2bfloat16(v.x - __bfloat162float(h0))),
               __bfloat16_as_ushort(__float2bfloat16(v.y - __bfloat162float(h1))));
}
__device__ __forceinline__ void split4(float4 v, uint2& hi, uint2& lo) {
    uint32_t h0, l0, h1, l1;
    split2(make_float2(v.x, v.y), h0, l0);
    split2(make_float2(v.z, v.w), h1, l1);
    hi = make_uint2(h0, h1); lo = make_uint2(l0, l1);
}

__global__ void __launch_bounds__(256, 1)
sdpa_hmma4_kernel(const float* __restrict__ gq, const float* __restrict__ gk,
                  const float* __restrict__ gv, const float* __restrict__ gkc,
                  const float* __restrict__ gvc, const int* __restrict__ gpos,
                  float* __restrict__ gout)
{
    extern __shared__ char smc[];
    const uint32_t sb = smem_u32(smc);
    const int tid = threadIdx.x;
    const int wid = tid >> 5;
    const int l   = tid & 31;
    const int bh = blockIdx.x, b = bh >> 5, h = bh & 31;

    const int start = *gpos;
    const int nkv   = start + Sc;
    const int nblk  = (nkv + KVB - 1) / KVB;

    const float* qb  = gq  + ((size_t)(b * Sc) * Hc + h) * Dc;
    const float* kcb = gkc + ((size_t)(b * Tc) * Hc + h) * Dc;
    const float* vcb = gvc + ((size_t)(b * Tc) * Hc + h) * Dc;
    const float* knb = gk  + ((size_t)(b * Sc) * Hc + h) * Dc;
    const float* vnb = gv  + ((size_t)(b * Sc) * Hc + h) * Dc;

    // per-thread staging coords (each thread converts exactly what it loads)
    // ---- cp.async block 0 into staging ----
    #pragma unroll
    for (int it = 0; it < 8; it++) {
        int idx = tid + it * 256;
        int key = idx >> 5, d = (idx & 31) * 4;
        int jg  = key;
        const float* ks; const float* vs;
        if (jg < start) { ks = kcb + (size_t)jg * HD + d;           vs = vcb + (size_t)jg * HD + d; }
        else            { ks = knb + (size_t)(jg - start) * HD + d; vs = vnb + (size_t)(jg - start) * HD + d; }
        cp16(sb + STGK + (uint32_t)idx * 16, ks);
        cp16(sb + STGV + (uint32_t)idx * 16, vs);
    }
    cp_commit();

    // ---- Q fragments in registers, scale*log2(e) folded in ----
    const int q0   = wid * 16;
    const int row0 = q0 + (l >> 2);
    const int cq   = (l & 3) * 2;
    const float SCALE = 0.08838834764831845f * 1.4426950408889634f;
    uint32_t qh[8][4], ql[8][4];
    #pragma unroll
    for (int ks = 0; ks < 8; ks++) {
        int c0 = ks * 16 + cq;
        float2 x[4];
        x[0] = *(const float2*)(qb + (size_t)row0 * HD + c0);
        x[1] = *(const float2*)(qb + (size_t)(row0 + 8) * HD + c0);
        x[2] = *(const float2*)(qb + (size_t)row0 * HD + c0 + 8);
        x[3] = *(const float2*)(qb + (size_t)(row0 + 8) * HD + c0 + 8);
        #pragma unroll
        for (int i = 0; i < 4; i++) {
            x[i].x *= SCALE; x[i].y *= SCALE;
            split2(x[i], qh[ks][i], ql[ks][i]);
        }
    }

    float O[16][4];
    #pragma unroll
    for (int t = 0; t < 16; t++) { O[t][0]=O[t][1]=O[t][2]=O[t][3]=0.f; }
    float lacc0 = 0.f, lacc1 = 0.f;

    // fragment address constants
    const int krow = (l & 7) + ((l >> 4) << 3);
    const int kc8  = ((l >> 3) & 1) << 3;
    const int vrow = (l & 7) + (((l >> 3) & 1) << 3);
    const int vc8  = (l >> 4) << 3;
    const int colb = (l & 3) * 2;

    // ---- convert block 0 staging -> bf16 buf 0 (self-data; no barrier needed) ----
    cp_wait0();
    #pragma unroll
    for (int it = 0; it < 8; it++) {
        int idx = tid + it * 256;
        int key = idx >> 5, d = (idx & 31) * 4;
        uint32_t o = swz_w(key, d);
        uint2 hi, lo;
        split4(*(const float4*)(smc + STGK + (size_t)idx * 16), hi, lo);
        *(uint2*)(smc + KHI + o) = hi; *(uint2*)(smc + KLO + o) = lo;
        split4(*(const float4*)(smc + STGV + (size_t)idx * 16), hi, lo);
        *(uint2*)(smc + VHI + o) = hi; *(uint2*)(smc + VLO + o) = lo;
    }
    __syncthreads();   // publish buf 0

    for (int blk = 0; blk < nblk; blk++) {
        const int t0 = blk * KVB;
        const bool pf = (blk + 1) < nblk;
        const uint32_t cur = (uint32_t)(blk & 1) * BUFS;
        const uint32_t nxt = cur ^ BUFS;

        // ---- cp.async next block into staging (background) ----
        if (pf) {
            const int t0n = t0 + KVB;
            #pragma unroll
            for (int it = 0; it < 8; it++) {
                int idx = tid + it * 256;
                int key = idx >> 5, d = (idx & 31) * 4;
                int jg  = t0n + key;
                const float* ks; const float* vs;
                if (jg < start) { ks = kcb + (size_t)jg * HD + d;           vs = vcb + (size_t)jg * HD + d; }
                else            { ks = knb + (size_t)(jg - start) * HD + d; vs = vnb + (size_t)(jg - start) * HD + d; }
                cp16(sb + STGK + (uint32_t)idx * 16, ks);
                cp16(sb + STGV + (uint32_t)idx * 16, vs);
            }
            cp_commit();
        }

        // ---- QK^T: per kstep, kh loads -> hixhi MMAs -> kl loads -> rest ----
        float S[8][4];
        #pragma unroll
        for (int t = 0; t < 8; t++) { S[t][0]=S[t][1]=S[t][2]=S[t][3]=0.f; }

        #pragma unroll
        for (int ks = 0; ks < 8; ks++) {
            int c0k = ks * 16 + kc8;
            uint32_t kh[4][4];
            #pragma unroll
            for (int np = 0; np < 4; np++) {
                uint32_t ko = swz_l(np * 16 + krow, c0k);
                LDSM4(kh[np][0],kh[np][1],kh[np][2],kh[np][3], sb + KHI + cur + ko);
            }
            #pragma unroll
            for (int np = 0; np < 4; np++) {   // term hi x hi
                MMA(S[2*np  ], qh[ks][0],qh[ks][1],qh[ks][2],qh[ks][3], kh[np][0],kh[np][1]);
                MMA(S[2*np+1], qh[ks][0],qh[ks][1],qh[ks][2],qh[ks][3], kh[np][2],kh[np][3]);
            }
            uint32_t kl[4][4];
            #pragma unroll
            for (int np = 0; np < 4; np++) {
                uint32_t ko = swz_l(np * 16 + krow, c0k);
                LDSM4(kl[np][0],kl[np][1],kl[np][2],kl[np][3], sb + KLO + cur + ko);
            }
            #pragma unroll
            for (int np = 0; np < 4; np++) {   // term lo x hi
                MMA(S[2*np  ], ql[ks][0],ql[ks][1],ql[ks][2],ql[ks][3], kh[np][0],kh[np][1]);
                MMA(S[2*np+1], ql[ks][0],ql[ks][1],ql[ks][2],ql[ks][3], kh[np][2],kh[np][3]);
            }
            #pragma unroll
            for (int np = 0; np < 4; np++) {   // term hi x lo
                MMA(S[2*np  ], qh[ks][0],qh[ks][1],qh[ks][2],qh[ks][3], kl[np][0],kl[np][1]);
                MMA(S[2*np+1], qh[ks][0],qh[ks][1],qh[ks][2],qh[ks][3], kl[np][2],kl[np][3]);
            }
        }

        // ---- softmax: exp2 (log2e folded into Q); mask only when needed ----
        uint32_t ph[4][4], pl[4][4];
        const bool needMask = (t0 + KVB - 1 > start);

#define SM_PACK(P0,P1,P2,P3,NT) { \
            lacc0 += (P0) + (P1);  lacc1 += (P2) + (P3); \
            __nv_bfloat16 b0 = __float2bfloat16(P0), b1 = __float2bfloat16(P1); \
            __nv_bfloat16 b2 = __float2bfloat16(P2), b3 = __float2bfloat16(P3); \
            int kg = (NT) >> 1, sl = ((NT) & 1) * 2; \
            ph[kg][sl  ] = pk_us(__bfloat16_as_ushort(b0), __bfloat16_as_ushort(b1)); \
            ph[kg][sl+1] = pk_us(__bfloat16_as_ushort(b2), __bfloat16_as_ushort(b3)); \
            pl[kg][sl  ] = pk_us( \
                __bfloat16_as_ushort(__float2bfloat16((P0) - __bfloat162float(b0))), \
                __bfloat16_as_ushort(__float2bfloat16((P1) - __bfloat162float(b1)))); \
            pl[kg][sl+1] = pk_us( \
                __bfloat16_as_ushort(__float2bfloat16((P2) - __bfloat162float(b2))), \
                __bfloat16_as_ushort(__float2bfloat16((P3) - __bfloat162float(b3)))); }

        if (!needMask) {
            #pragma unroll
            for (int nt = 0; nt < 8; nt++) {
                float p0 = exp2f(S[nt][0]);
                float p1 = exp2f(S[nt][1]);
                float p2 = exp2f(S[nt][2]);
                float p3 = exp2f(S[nt][3]);
                SM_PACK(p0, p1, p2, p3, nt);
            }
        } else {
            #pragma unroll
            for (int nt = 0; nt < 8; nt++) {
                int j0 = t0 + nt * 8 + colb - start;
                float p0 = (j0     > row0    ) ? 0.f : exp2f(S[nt][0]);
                float p1 = (j0 + 1 > row0    ) ? 0.f : exp2f(S[nt][1]);
                float p2 = (j0     > row0 + 8) ? 0.f : exp2f(S[nt][2]);
                float p3 = (j0 + 1 > row0 + 8) ? 0.f : exp2f(S[nt][3]);
                SM_PACK(p0, p1, p2, p3, nt);
            }
        }
#undef SM_PACK

        // ---- PV: d-tile pairs, term-major ----
        #pragma unroll
        for (int kg = 0; kg < 4; kg++) {
            int vr = kg * 16 + vrow;
            #pragma unroll
            for (int dq = 0; dq < 4; dq++) {
                uint32_t vh[2][4], vl[2][4];
                #pragma unroll
                for (int u = 0; u < 2; u++) {
                    uint32_t vo = swz_l(vr, (dq * 2 + u) * 16 + vc8);
                    LDSM4T(vh[u][0],vh[u][1],vh[u][2],vh[u][3], sb + VHI + cur + vo);
                    LDSM4T(vl[u][0],vl[u][1],vl[u][2],vl[u][3], sb + VLO + cur + vo);
                }
                #pragma unroll
                for (int u = 0; u < 2; u++) {
                    MMA(O[2*(dq*2+u)  ], ph[kg][0],ph[kg][1],ph[kg][2],ph[kg][3], vh[u][0],vh[u][1]);
                    MMA(O[2*(dq*2+u)+1], ph[kg][0],ph[kg][1],ph[kg][2],ph[kg][3], vh[u][2],vh[u][3]);
                }
                #pragma unroll
                for (int u = 0; u < 2; u++) {
                    MMA(O[2*(dq*2+u)  ], ph[kg][0],ph[kg][1],ph[kg][2],ph[kg][3], vl[u][0],vl[u][1]);
                    MMA(O[2*(dq*2+u)+1], ph[kg][0],ph[kg][1],ph[kg][2],ph[kg][3], vl[u][2],vl[u][3]);
                }
                #pragma unroll
                for (int u = 0; u < 2; u++) {
                    MMA(O[2*(dq*2+u)  ], pl[kg][0],pl[kg][1],pl[kg][2],pl[kg][3], vh[u][0],vh[u][1]);
                    MMA(O[2*(dq*2+u)+1], pl[kg][0],pl[kg][1],pl[kg][2],pl[kg][3], vh[u][2],vh[u][3]);
                }
            }
        }

        // ---- convert staging -> next buffer; single barrier publishes it ----
        if (pf) {
            cp_wait0();
            #pragma unroll
            for (int it = 0; it < 8; it++) {
                int idx = tid + it * 256;
                int key = idx >> 5, d = (idx & 31) * 4;
                uint32_t o = swz_w(key, d);
                uint2 hi, lo;
                split4(*(const float4*)(smc + STGK + (size_t)idx * 16), hi, lo);
                *(uint2*)(smc + KHI + nxt + o) = hi; *(uint2*)(smc + KLO + nxt + o) = lo;
                split4(*(const float4*)(smc + STGV + (size_t)idx * 16), hi, lo);
                *(uint2*)(smc + VHI + nxt + o) = hi; *(uint2*)(smc + VLO + nxt + o) = lo;
            }
            __syncthreads();
        }
    }

    // ---- epilogue: quad row-sum reduce, normalize, store ----
    lacc0 += __shfl_xor_sync(0xffffffffu, lacc0, 1);
    lacc0 += __shfl_xor_sync(0xffffffffu, lacc0, 2);
    lacc1 += __shfl_xor_sync(0xffffffffu, lacc1, 1);
    lacc1 += __shfl_xor_sync(0xffffffffu, lacc1, 2);
    const float inv0 = 1.f / lacc0, inv1 = 1.f / lacc1;

    float* o0 = gout + ((size_t)(b * Sc + row0    ) * HD) + h * Dc;
    float* o1 = gout + ((size_t)(b * Sc + row0 + 8) * HD) + h * Dc;
    #pragma unroll
    for (int nt = 0; nt < 16; nt++) {
        int d = nt * 8 + colb;
        *(float2*)(o0 + d) = make_float2(O[nt][0] * inv0, O[nt][1] * inv0);
        *(float2*)(o1 + d) = make_float2(O[nt][2] * inv1, O[nt][3] * inv1);
    }
}

extern "C" void kernel_launch(void* const* d_in, const int* in_sizes, int n_in,
                              void* d_out, int out_size)
{
    const float* q  = (const float*)d_in[0];
    const float* k  = (const float*)d_in[1];
    const float* v  = (const float*)d_in[2];
    const float* kc = (const float*)d_in[3];
    const float* vc = (const float*)d_in[4];
    const int*  pos = (const int*)d_in[5];
    float* out = (float*)d_out;

    cudaFuncSetAttribute(sdpa_hmma4_kernel,
                         cudaFuncAttributeMaxDynamicSharedMemorySize, SMEM_BYTES);
    sdpa_hmma4_kernel<<<Bc * Hc, 256, SMEM_BYTES>>>(q, k, v, kc, vc, pos, out);
}